// round 1
// baseline (speedup 1.0000x reference)
#include <cuda_runtime.h>
#include <cstdint>

#define N_NODES 4096
#define F_OUT   512
#define R_REL   474
#define IN_RELS 500
#define N_EDGES 131072
#define MAXDEG  512   // expected max row fill ~120; 512 is very safe

// ---------------- static device scratch (no allocations allowed) ----------------
__device__ int      g_idx64;                       // 1 if index arrays are int64
__device__ int      g_count[N_NODES];              // per-row bucket fill
__device__ uint32_t g_bucket[N_NODES * MAXDEG];    // packed (col<<19 | key)
__device__ float    g_s[R_REL];                    // per-relation score
__device__ float    g_rv[N_EDGES];                 // relu(score) per edge

// ---------------- init: zero counters + detect index dtype ----------------
__global__ void k_init(const void* __restrict__ edge_src) {
    int t = blockIdx.x * blockDim.x + threadIdx.x;
    if (t < N_NODES) g_count[t] = 0;
    if (t == 0) {
        // int64 little-endian: every odd 32-bit word is the (zero) high half.
        // int32: odd words are random values in [0,4096); all-zero is impossible.
        const int* w = (const int*)edge_src;
        int is64 = 1;
        for (int i = 0; i < 128; i++) {
            if (w[2 * i + 1] != 0) { is64 = 0; break; }
        }
        g_idx64 = is64;
    }
}

// ---------------- per-relation score: s[r] = rel[r] . w_rel ----------------
__global__ __launch_bounds__(128) void k_score(const float* __restrict__ rel,
                                               const float* __restrict__ w_rel) {
    int r = blockIdx.x;
    const float* row = rel + (size_t)r * IN_RELS;
    float acc = 0.f;
    for (int k = threadIdx.x; k < IN_RELS; k += 128) acc += row[k] * w_rel[k];
    for (int o = 16; o; o >>= 1) acc += __shfl_down_sync(0xffffffffu, acc, o);
    __shared__ float sm[4];
    if ((threadIdx.x & 31) == 0) sm[threadIdx.x >> 5] = acc;
    __syncthreads();
    if (threadIdx.x == 0) g_s[r] = sm[0] + sm[1] + sm[2] + sm[3];
}

// ---------------- scatter edges into per-row buckets ----------------
// Priority replicates the reference's two sequential scatters:
//   phase1 (src,dst) key = e+1 ; phase2 (dst,src) key = E+e+1 ; larger key wins.
__global__ __launch_bounds__(256) void k_scatter(const void* __restrict__ esrc,
                                                 const void* __restrict__ edst,
                                                 const void* __restrict__ ridx) {
    int e = blockIdx.x * blockDim.x + threadIdx.x;
    if (e >= N_EDGES) return;
    int src, dst, r;
    if (g_idx64) {
        src = (int)((const long long*)esrc)[e];
        dst = (int)((const long long*)edst)[e];
        r   = (int)((const long long*)ridx)[e];
    } else {
        src = ((const int*)esrc)[e];
        dst = ((const int*)edst)[e];
        r   = ((const int*)ridx)[e];
    }
    float v = g_s[r];
    g_rv[e] = v > 0.f ? v : 0.f;   // relu applied once here

    uint32_t p1 = ((uint32_t)dst << 19) | (uint32_t)(e + 1);
    int pos1 = atomicAdd(&g_count[src], 1);
    if (pos1 < MAXDEG) g_bucket[src * MAXDEG + pos1] = p1;

    uint32_t p2 = ((uint32_t)src << 19) | (uint32_t)(N_EDGES + e + 1);
    int pos2 = atomicAdd(&g_count[dst], 1);
    if (pos2 < MAXDEG) g_bucket[dst * MAXDEG + pos2] = p2;
}

// ---------------- per-row: dedup, softmax, weighted gather, elu ----------------
__global__ __launch_bounds__(128) void k_row(const float* __restrict__ input,
                                             const float* __restrict__ bias,
                                             float* __restrict__ out) {
    __shared__ uint32_t sp[MAXDEG];
    __shared__ int      scol[MAXDEG + 1];
    __shared__ float    sval[MAXDEG + 1];
    __shared__ int      s_nv, s_diag;
    __shared__ float    s_red[4];
    __shared__ float    s_m, s_inv;

    int row = blockIdx.x;
    int t = threadIdx.x;

    int cnt = g_count[row];
    if (cnt > MAXDEG) cnt = MAXDEG;
    if (t == 0) { s_nv = 0; s_diag = 0; }
    for (int k = t; k < cnt; k += 128) sp[k] = g_bucket[row * MAXDEG + k];
    __syncthreads();

    // dedup: for a duplicated column keep the entry with the largest key.
    // packed = (col<<19)|key, so for equal col a larger packed means larger key.
    for (int k = t; k < cnt; k += 128) {
        uint32_t p = sp[k];
        uint32_t col = p >> 19;
        bool valid = true;
        for (int j = 0; j < cnt; j++) {
            uint32_t q = sp[j];
            if ((q >> 19) == col && q > p) { valid = false; break; }
        }
        if (valid) {
            int e = (int)(p & 0x7FFFFu) - 1;
            if (e >= N_EDGES) e -= N_EDGES;
            int pos = atomicAdd(&s_nv, 1);
            scol[pos] = (int)col;
            sval[pos] = g_rv[e];
            if ((int)col == row) s_diag = 1;
        }
    }
    __syncthreads();

    // diagonal always in the softmax support (adj[i,i]=0); logit 0 if no self-edge
    if (t == 0 && !s_diag) { int nv = s_nv; scol[nv] = row; sval[nv] = 0.f; s_nv = nv + 1; }
    __syncthreads();
    int nv = s_nv;

    // max (all vals >= 0, so 0 is a safe identity)
    float m = 0.f;
    for (int k = t; k < nv; k += 128) m = fmaxf(m, sval[k]);
    for (int o = 16; o; o >>= 1) m = fmaxf(m, __shfl_xor_sync(0xffffffffu, m, o));
    if ((t & 31) == 0) s_red[t >> 5] = m;
    __syncthreads();
    if (t == 0) s_m = fmaxf(fmaxf(s_red[0], s_red[1]), fmaxf(s_red[2], s_red[3]));
    __syncthreads();
    m = s_m;

    // exp + sum
    float ssum = 0.f;
    for (int k = t; k < nv; k += 128) {
        float p = expf(sval[k] - m);
        sval[k] = p;
        ssum += p;
    }
    for (int o = 16; o; o >>= 1) ssum += __shfl_xor_sync(0xffffffffu, ssum, o);
    if ((t & 31) == 0) s_red[t >> 5] = ssum;
    __syncthreads();
    if (t == 0) s_inv = 1.f / (s_red[0] + s_red[1] + s_red[2] + s_red[3]);
    __syncthreads();
    float inv = s_inv;

    // weighted gather of input rows; thread t owns float4 column block t (cols 4t..4t+3)
    const float4* in4 = (const float4*)input;
    float4 acc = ((const float4*)bias)[t];
    int k = 0;
    for (; k + 4 <= nv; k += 4) {
        int c0 = scol[k], c1 = scol[k + 1], c2 = scol[k + 2], c3 = scol[k + 3];
        float w0 = sval[k] * inv, w1 = sval[k + 1] * inv,
              w2 = sval[k + 2] * inv, w3 = sval[k + 3] * inv;
        float4 x0 = in4[c0 * 128 + t];
        float4 x1 = in4[c1 * 128 + t];
        float4 x2 = in4[c2 * 128 + t];
        float4 x3 = in4[c3 * 128 + t];
        acc.x += w0 * x0.x + w1 * x1.x + w2 * x2.x + w3 * x3.x;
        acc.y += w0 * x0.y + w1 * x1.y + w2 * x2.y + w3 * x3.y;
        acc.z += w0 * x0.z + w1 * x1.z + w2 * x2.z + w3 * x3.z;
        acc.w += w0 * x0.w + w1 * x1.w + w2 * x2.w + w3 * x3.w;
    }
    for (; k < nv; k++) {
        int c = scol[k];
        float w = sval[k] * inv;
        float4 x = in4[c * 128 + t];
        acc.x += w * x.x; acc.y += w * x.y; acc.z += w * x.z; acc.w += w * x.w;
    }

    // elu (alpha=1)
    acc.x = acc.x > 0.f ? acc.x : expm1f(acc.x);
    acc.y = acc.y > 0.f ? acc.y : expm1f(acc.y);
    acc.z = acc.z > 0.f ? acc.z : expm1f(acc.z);
    acc.w = acc.w > 0.f ? acc.w : expm1f(acc.w);
    ((float4*)out)[row * 128 + t] = acc;
}

// ---------------- launch ----------------
extern "C" void kernel_launch(void* const* d_in, const int* in_sizes, int n_in,
                              void* d_out, int out_size) {
    const float* input = (const float*)d_in[0];   // [4096, 512]
    const float* rel   = (const float*)d_in[1];   // [474, 500]
    // d_in[2] = adj [4096,4096]  -- intentionally unused (mask reconstructed from edges)
    const float* w_rel = (const float*)d_in[3];   // [500]
    const float* bias  = (const float*)d_in[4];   // [512]
    const void*  esrc  = d_in[5];                 // [131072] int32 or int64
    const void*  edst  = d_in[6];
    // d_in[7] = rel_edge_id (arange) -- unused, segment_max is an identity gather
    const void*  ridx  = d_in[8];
    float* out = (float*)d_out;                   // [4096, 512]

    k_init<<<(N_NODES + 511) / 512, 512>>>(esrc);
    k_score<<<R_REL, 128>>>(rel, w_rel);
    k_scatter<<<(N_EDGES + 255) / 256, 256>>>(esrc, edst, ridx);
    k_row<<<N_NODES, 128>>>(input, bias, out);
}